// round 5
// baseline (speedup 1.0000x reference)
#include <cuda_runtime.h>
#include <cuda_fp16.h>
#include <cstdint>

// Fused QKV projection: X[16384,1024] @ [Wq|Wk|Wv][1024,3072] + bias,
// head-split epilogue. fp16 mma.sync.m16n8k16 (fp32 accum).
//
// Prep A: X -> fp16, m16n8k16 A-fragment order.
// Prep B: W -> fp16, B-fragment order per 64-col block.
// GEMM: CTA 128x256, 8 warps (warp 64x64), BK=64, 3-stage cp.async,
//       single __syncthreads per stage, loads issued after barrier.

#define MDIM 16384
#define KDIM 1024
#define NTOT 3072
#define BM 128
#define BN 256
#define BK 64
#define NKT (KDIM / BK)          // 16
#define NSTAGE 3
#define A_BYTES 16384            // 8 mtiles x 4 kc x 512B
#define B_BYTES 32768            // 4 nblk64 x 4 kc x 4 c x 512B
#define STAGE_BYTES (A_BYTES + B_BYTES)       // 49152
#define SMEM_TOTAL (NSTAGE * STAGE_BYTES)     // 147456
#define OUT_PER_MAT (4 * 16 * 4096 * 64)

__device__ uint4 g_A[(size_t)1024 * 64 * 32];      // 32 MB
__device__ uint4 g_B[(size_t)48 * 64 * 4 * 32];    // 6 MB

__device__ __forceinline__ uint32_t h2u(float a, float b) {
    __half2 h = __float22half2_rn(make_float2(a, b));
    return *reinterpret_cast<uint32_t*>(&h);
}
__device__ __forceinline__ uint32_t smem_u32(const void* p) {
    uint32_t a;
    asm("{ .reg .u64 t; cvta.to.shared.u64 t, %1; cvt.u32.u64 %0, t; }" : "=r"(a) : "l"(p));
    return a;
}
__device__ __forceinline__ void cp16(uint32_t dst, const void* src) {
    asm volatile("cp.async.cg.shared.global [%0], [%1], 16;" :: "r"(dst), "l"(src));
}
__device__ __forceinline__ void mma_f16(float* c, const uint4& a, uint32_t b0, uint32_t b1) {
    asm volatile(
        "mma.sync.aligned.m16n8k16.row.col.f32.f16.f16.f32 "
        "{%0,%1,%2,%3},{%4,%5,%6,%7},{%8,%9},{%0,%1,%2,%3};"
        : "+f"(c[0]), "+f"(c[1]), "+f"(c[2]), "+f"(c[3])
        : "r"(a.x), "r"(a.y), "r"(a.z), "r"(a.w), "r"(b0), "r"(b1));
}

// ---------------- prep kernels ----------------
// A fragment (m16n8k16, row-major A 16x16): lane (g,t):
//   a0={A[g][2t],A[g][2t+1]} a1={A[g+8][2t],..} a2={A[g][2t+8],..} a3={A[g+8][2t+8],..}
__global__ void __launch_bounds__(256) prep_a(const float* __restrict__ X) {
    const int tId = blockIdx.x * 8 + (threadIdx.x >> 5);   // 65536 tiles
    const int lane = threadIdx.x & 31;
    const int g = lane >> 2, t = lane & 3;
    const int mt = tId >> 6, kt = tId & 63;
    const int r0 = mt * 16 + g;
    const int c0 = kt * 16 + 2 * t;
    const float2* x0 = reinterpret_cast<const float2*>(X + (size_t)r0 * KDIM + c0);
    const float2* x1 = reinterpret_cast<const float2*>(X + (size_t)(r0 + 8) * KDIM + c0);
    float2 v00 = x0[0], v02 = x0[4];
    float2 v10 = x1[0], v12 = x1[4];
    uint4 o;
    o.x = h2u(v00.x, v00.y);
    o.y = h2u(v10.x, v10.y);
    o.z = h2u(v02.x, v02.y);
    o.w = h2u(v12.x, v12.y);
    g_A[(size_t)tId * 32 + lane] = o;
}

// B fragment (k16 x n8, "col"): lane (g,t):
//   b0={B[2t][g],B[2t+1][g]}  b1={B[2t+8][g],B[2t+9][g]}
// chunk c packs ntiles 2c and 2c+1.
__global__ void __launch_bounds__(256) prep_b(const float* __restrict__ Wq,
                                              const float* __restrict__ Wk,
                                              const float* __restrict__ Wv) {
    const int wId = blockIdx.x * 8 + (threadIdx.x >> 5);   // 12288 warps
    const int lane = threadIdx.x & 31;
    const int g = lane >> 2, t = lane & 3;
    const int nb = wId >> 8;          // 0..47
    const int kk = (wId >> 2) & 63;   // ktile16
    const int c = wId & 3;            // chunk
    const int n0 = nb * 64 + (2 * c) * 8 + g;
    const int n1 = n0 + 8;
    const float* W = (n0 < 1024) ? Wq : (n0 < 2048) ? Wk : Wv;
    const int nc0 = n0 & 1023, nc1 = n1 & 1023;
    const int k0 = kk * 16 + 2 * t;
    uint4 o;
    o.x = h2u(W[(size_t)k0 * 1024 + nc0],       W[(size_t)(k0 + 1) * 1024 + nc0]);
    o.y = h2u(W[(size_t)(k0 + 8) * 1024 + nc0], W[(size_t)(k0 + 9) * 1024 + nc0]);
    o.z = h2u(W[(size_t)k0 * 1024 + nc1],       W[(size_t)(k0 + 1) * 1024 + nc1]);
    o.w = h2u(W[(size_t)(k0 + 8) * 1024 + nc1], W[(size_t)(k0 + 9) * 1024 + nc1]);
    g_B[((size_t)(nb * 64 + kk) * 4 + c) * 32 + lane] = o;
}

// ---------------- GEMM ----------------
__global__ void __launch_bounds__(256, 1)
qkv_f16_mma(const float* __restrict__ bq, const float* __restrict__ bk,
            const float* __restrict__ bv, float* __restrict__ out) {
    extern __shared__ char smem[];
    const uint32_t sb = smem_u32(smem);
    const int tid = threadIdx.x;
    const int warp = tid >> 5;
    const int lane = tid & 31;
    const int g = lane >> 2, t = lane & 3;
    const int warpRow = warp >> 2;   // 0..1  (64 rows each)
    const int warpCol = warp & 3;    // 0..3  (64 cols each)

    const int nblk = blockIdx.x;         // 0..11
    const int mblk = blockIdx.y;         // 0..127
    const int mat = nblk >> 2;           // 0=q,1=k,2=v
    const int n0w = (nblk & 3) * BN;     // n within matrix [0,1024)
    const int m0 = mblk * BM;
    const int mtile0 = mblk * 8;
    const int nb0 = nblk * 4;            // global 64-col block index
    const float* bias = (mat == 0) ? bq : (mat == 1) ? bk : bv;

    float acc[4][8][4];
#pragma unroll
    for (int i = 0; i < 4; i++)
#pragma unroll
        for (int j = 0; j < 8; j++)
#pragma unroll
            for (int r = 0; r < 4; r++) acc[i][j][r] = 0.0f;

    // A smem: [mt(8)][kc(4)][lane(32)] x 16B
    // B smem: [nbL(4)][kc(4)][c(4)][lane(32)] x 16B
    auto load_stage = [&](int s, int kt) {
        const uint32_t aB = sb + s * STAGE_BYTES;
        const uint32_t bB = aB + A_BYTES;
#pragma unroll
        for (int i = 0; i < 4; i++) {   // A: 1024 x 16B
            int chunk = tid + i * 256;
            int b = chunk >> 5, l = chunk & 31;
            int mt_i = b >> 2, kc = b & 3;
            cp16(aB + chunk * 16,
                 g_A + ((size_t)(mtile0 + mt_i) * 64 + kt * 4 + kc) * 32 + l);
        }
#pragma unroll
        for (int i = 0; i < 8; i++) {   // B: 2048 x 16B
            int chunk = tid + i * 256;
            int b = chunk >> 5, l = chunk & 31;
            int nbL = b >> 4, kc = (b >> 2) & 3, c = b & 3;
            cp16(bB + chunk * 16,
                 g_B + ((size_t)((nb0 + nbL) * 64 + kt * 4 + kc) * 4 + c) * 32 + l);
        }
        asm volatile("cp.async.commit_group;" ::: "memory");
    };

    load_stage(0, 0);
    load_stage(1, 1);

    for (int kt = 0; kt < NKT; kt++) {
        const int s = kt % NSTAGE;
        if (kt + 2 < NKT)
            asm volatile("cp.async.wait_group 1;" ::: "memory");
        else
            asm volatile("cp.async.wait_group 0;" ::: "memory");
        __syncthreads();

        // Refill buffer (kt+2)%3: its old contents (stage kt-1) were consumed
        // by all warps before the barrier above.
        if (kt + 2 < NKT) load_stage((kt + 2) % NSTAGE, kt + 2);

        const char* aP = smem + s * STAGE_BYTES;
        const char* bP = aP + A_BYTES;
#pragma unroll
        for (int kc = 0; kc < 4; kc++) {
            uint4 af[4];
#pragma unroll
            for (int mtl = 0; mtl < 4; mtl++)
                af[mtl] = *reinterpret_cast<const uint4*>(
                    aP + (((warpRow * 4 + mtl) * 4 + kc) * 32 + lane) * 16);
            uint4 bf[4];
#pragma unroll
            for (int c = 0; c < 4; c++)
                bf[c] = *reinterpret_cast<const uint4*>(
                    bP + ((((size_t)warpCol * 4 + kc) * 4 + c) * 32 + lane) * 16);
#pragma unroll
            for (int mtl = 0; mtl < 4; mtl++)
#pragma unroll
                for (int nt = 0; nt < 8; nt++) {
                    const uint4& b = bf[nt >> 1];
                    uint32_t b0 = (nt & 1) ? b.z : b.x;
                    uint32_t b1 = (nt & 1) ? b.w : b.y;
                    mma_f16(acc[mtl][nt], af[mtl], b0, b1);
                }
        }
    }

    // ---- epilogue: bias + head-split scatter ----
    float* outm = out + (size_t)mat * OUT_PER_MAT;
#pragma unroll
    for (int mtl = 0; mtl < 4; mtl++) {
#pragma unroll
        for (int rh = 0; rh < 2; rh++) {
            const int row = m0 + warpRow * 64 + mtl * 16 + g + rh * 8;
            const int bb = row >> 12;
            const int sq = row & 4095;
#pragma unroll
            for (int nt = 0; nt < 8; nt++) {
                const int nloc = n0w + warpCol * 64 + nt * 8 + 2 * t;
                const int head = nloc >> 6;
                const int d = nloc & 63;
                const float v0 = acc[mtl][nt][rh * 2 + 0] + bias[nloc];
                const float v1 = acc[mtl][nt][rh * 2 + 1] + bias[nloc + 1];
                const size_t idx = ((size_t)((bb * 16 + head) * 4096 + sq)) * 64 + d;
                *reinterpret_cast<float2*>(outm + idx) = make_float2(v0, v1);
            }
        }
    }
}

// ---------------- launch ----------------
extern "C" void kernel_launch(void* const* d_in, const int* in_sizes, int n_in,
                              void* d_out, int out_size) {
    const float* X  = (const float*)d_in[0];
    const float* Wq = (const float*)d_in[1];
    const float* bq = (const float*)d_in[2];
    const float* Wk = (const float*)d_in[3];
    const float* bk = (const float*)d_in[4];
    const float* Wv = (const float*)d_in[5];
    const float* bv = (const float*)d_in[6];
    float* out = (float*)d_out;

    prep_a<<<8192, 256>>>(X);
    prep_b<<<1536, 256>>>(Wq, Wk, Wv);

    cudaFuncSetAttribute(qkv_f16_mma,
                         cudaFuncAttributeMaxDynamicSharedMemorySize, SMEM_TOTAL);
    qkv_f16_mma<<<dim3(12, 128), 256, SMEM_TOTAL>>>(bq, bk, bv, out);
}

// round 6
// speedup vs baseline: 1.1627x; 1.1627x over previous
#include <cuda_runtime.h>
#include <cuda_fp16.h>
#include <cstdint>

// Fused QKV projection: X[16384,1024] @ [Wq|Wk|Wv][1024,3072] + bias,
// head-split epilogue. fp16 mma.sync.m16n8k16 (fp32 accum).
//
// GEMM: CTA 128x128, 4 warps (2x2 grid of 64x64 warp tiles), BK=32,
//       4-stage cp.async, 64KB smem -> 3 CTAs/SM (12 warps), regs<=170.

#define MDIM 16384
#define KDIM 1024
#define NTOT 3072
#define BM 128
#define BN 128
#define BK 32
#define NKT (KDIM / BK)          // 32
#define NSTAGE 4
#define A_BYTES 8192             // 8 mt x 2 kc x 512B
#define B_BYTES 8192             // 2 nbL x 2 kc x 4 c x 512B
#define STAGE_BYTES (A_BYTES + B_BYTES)       // 16384
#define SMEM_TOTAL (NSTAGE * STAGE_BYTES)     // 65536
#define OUT_PER_MAT (4 * 16 * 4096 * 64)

__device__ uint4 g_A[(size_t)1024 * 64 * 32];      // 32 MB
__device__ uint4 g_B[(size_t)48 * 64 * 4 * 32];    // 6 MB

__device__ __forceinline__ uint32_t h2u(float a, float b) {
    __half2 h = __float22half2_rn(make_float2(a, b));
    return *reinterpret_cast<uint32_t*>(&h);
}
__device__ __forceinline__ uint32_t smem_u32(const void* p) {
    uint32_t a;
    asm("{ .reg .u64 t; cvta.to.shared.u64 t, %1; cvt.u32.u64 %0, t; }" : "=r"(a) : "l"(p));
    return a;
}
__device__ __forceinline__ void cp16(uint32_t dst, const void* src) {
    asm volatile("cp.async.cg.shared.global [%0], [%1], 16;" :: "r"(dst), "l"(src));
}
__device__ __forceinline__ void mma_f16(float* c, const uint4& a, uint32_t b0, uint32_t b1) {
    asm volatile(
        "mma.sync.aligned.m16n8k16.row.col.f32.f16.f16.f32 "
        "{%0,%1,%2,%3},{%4,%5,%6,%7},{%8,%9},{%0,%1,%2,%3};"
        : "+f"(c[0]), "+f"(c[1]), "+f"(c[2]), "+f"(c[3])
        : "r"(a.x), "r"(a.y), "r"(a.z), "r"(a.w), "r"(b0), "r"(b1));
}

// ---------------- prep kernels ----------------
// A fragment (m16n8k16, row-major A 16x16), lane (g,t):
//   a0={A[g][2t],A[g][2t+1]} a1={A[g+8][..]} a2={A[g][2t+8],..} a3={A[g+8][2t+8],..}
__global__ void __launch_bounds__(256) prep_a(const float* __restrict__ X) {
    const int tId = blockIdx.x * 8 + (threadIdx.x >> 5);   // 65536 tiles
    const int lane = threadIdx.x & 31;
    const int g = lane >> 2, t = lane & 3;
    const int mt = tId >> 6, kt = tId & 63;
    const int r0 = mt * 16 + g;
    const int c0 = kt * 16 + 2 * t;
    const float2* x0 = reinterpret_cast<const float2*>(X + (size_t)r0 * KDIM + c0);
    const float2* x1 = reinterpret_cast<const float2*>(X + (size_t)(r0 + 8) * KDIM + c0);
    float2 v00 = x0[0], v02 = x0[4];
    float2 v10 = x1[0], v12 = x1[4];
    uint4 o;
    o.x = h2u(v00.x, v00.y);
    o.y = h2u(v10.x, v10.y);
    o.z = h2u(v02.x, v02.y);
    o.w = h2u(v12.x, v12.y);
    g_A[(size_t)tId * 32 + lane] = o;
}

// B fragment (k16 x n8 "col"), lane (g,t):
//   b0={B[2t][g],B[2t+1][g]}  b1={B[2t+8][g],B[2t+9][g]}
// chunk c packs ntiles 2c and 2c+1.
__global__ void __launch_bounds__(256) prep_b(const float* __restrict__ Wq,
                                              const float* __restrict__ Wk,
                                              const float* __restrict__ Wv) {
    const int wId = blockIdx.x * 8 + (threadIdx.x >> 5);   // 12288 warps
    const int lane = threadIdx.x & 31;
    const int g = lane >> 2, t = lane & 3;
    const int nb = wId >> 8;          // 0..47
    const int kk = (wId >> 2) & 63;   // ktile16
    const int c = wId & 3;            // chunk
    const int n0 = nb * 64 + (2 * c) * 8 + g;
    const int n1 = n0 + 8;
    const float* W = (n0 < 1024) ? Wq : (n0 < 2048) ? Wk : Wv;
    const int nc0 = n0 & 1023, nc1 = n1 & 1023;
    const int k0 = kk * 16 + 2 * t;
    uint4 o;
    o.x = h2u(W[(size_t)k0 * 1024 + nc0],       W[(size_t)(k0 + 1) * 1024 + nc0]);
    o.y = h2u(W[(size_t)(k0 + 8) * 1024 + nc0], W[(size_t)(k0 + 9) * 1024 + nc0]);
    o.z = h2u(W[(size_t)k0 * 1024 + nc1],       W[(size_t)(k0 + 1) * 1024 + nc1]);
    o.w = h2u(W[(size_t)(k0 + 8) * 1024 + nc1], W[(size_t)(k0 + 9) * 1024 + nc1]);
    g_B[((size_t)(nb * 64 + kk) * 4 + c) * 32 + lane] = o;
}

// ---------------- GEMM ----------------
__global__ void __launch_bounds__(128, 3)
qkv_f16_mma(const float* __restrict__ bq, const float* __restrict__ bk,
            const float* __restrict__ bv, float* __restrict__ out) {
    extern __shared__ char smem[];
    const uint32_t sb = smem_u32(smem);
    const int tid = threadIdx.x;
    const int warp = tid >> 5;
    const int lane = tid & 31;
    const int g = lane >> 2, t = lane & 3;
    const int warpRow = warp >> 1;   // 0..1 (64 rows)
    const int warpCol = warp & 1;    // 0..1 (64 cols)

    const int nblk = blockIdx.x;         // 0..23
    const int mblk = blockIdx.y;         // 0..127
    const int mat = nblk >> 3;
    const int n0w = (nblk & 7) * BN;     // n within matrix
    const int m0 = mblk * BM;
    const int mtile0 = mblk * 8;
    const int nb0 = nblk * 2;            // global 64-col block index
    const float* bias = (mat == 0) ? bq : (mat == 1) ? bk : bv;

    float acc[4][8][4];
#pragma unroll
    for (int i = 0; i < 4; i++)
#pragma unroll
        for (int j = 0; j < 8; j++)
#pragma unroll
            for (int r = 0; r < 4; r++) acc[i][j][r] = 0.0f;

    // A smem: [mt(8)][kc(2)][lane(32)] x 16B
    // B smem: [nbL(2)][kc(2)][c(4)][lane(32)] x 16B
    auto load_stage = [&](int s, int kt) {
        const uint32_t aB = sb + s * STAGE_BYTES;
        const uint32_t bB = aB + A_BYTES;
#pragma unroll
        for (int i = 0; i < 4; i++) {   // A: 512 x 16B
            int chunk = tid + i * 128;
            int b = chunk >> 5, l = chunk & 31;
            int mt_i = b >> 1, kc = b & 1;
            cp16(aB + chunk * 16,
                 g_A + ((size_t)(mtile0 + mt_i) * 64 + kt * 2 + kc) * 32 + l);
        }
#pragma unroll
        for (int i = 0; i < 4; i++) {   // B: 512 x 16B
            int chunk = tid + i * 128;
            int b = chunk >> 5, l = chunk & 31;
            int nbL = b >> 3, kc = (b >> 2) & 1, c = b & 3;
            cp16(bB + chunk * 16,
                 g_B + ((size_t)((nb0 + nbL) * 64 + kt * 2 + kc) * 4 + c) * 32 + l);
        }
        asm volatile("cp.async.commit_group;" ::: "memory");
    };

    load_stage(0, 0);
    load_stage(1, 1);
    load_stage(2, 2);

    for (int kt = 0; kt < NKT; kt++) {
        const int s = kt & 3;
        asm volatile("cp.async.wait_group 2;" ::: "memory");
        __syncthreads();
        // Refill buffer (kt+3)&3: its old contents (stage kt-1) were consumed
        // by all warps before the barrier above.
        if (kt + 3 < NKT) load_stage((kt + 3) & 3, kt + 3);

        const char* aP = smem + s * STAGE_BYTES;
        const char* bP = aP + A_BYTES;
#pragma unroll
        for (int kc = 0; kc < 2; kc++) {
            uint4 af[4];
#pragma unroll
            for (int mtl = 0; mtl < 4; mtl++)
                af[mtl] = *reinterpret_cast<const uint4*>(
                    aP + (((warpRow * 4 + mtl) * 2 + kc) * 32 + lane) * 16);
#pragma unroll
            for (int c = 0; c < 4; c++) {
                // load one B chunk (4 regs live), do 8 MMAs with it
                uint4 b = *reinterpret_cast<const uint4*>(
                    bP + (((warpCol * 2 + kc) * 4 + c) * 32 + lane) * 16);
#pragma unroll
                for (int mtl = 0; mtl < 4; mtl++) {
                    mma_f16(acc[mtl][2 * c + 0], af[mtl], b.x, b.y);
                    mma_f16(acc[mtl][2 * c + 1], af[mtl], b.z, b.w);
                }
            }
        }
    }
    asm volatile("cp.async.wait_group 0;" ::: "memory");

    // ---- epilogue: bias + head-split scatter ----
    float* outm = out + (size_t)mat * OUT_PER_MAT;
#pragma unroll
    for (int mtl = 0; mtl < 4; mtl++) {
#pragma unroll
        for (int rh = 0; rh < 2; rh++) {
            const int row = m0 + warpRow * 64 + mtl * 16 + g + rh * 8;
            const int bb = row >> 12;
            const int sq = row & 4095;
#pragma unroll
            for (int nt = 0; nt < 8; nt++) {
                const int nloc = n0w + warpCol * 64 + nt * 8 + 2 * t;
                const int head = nloc >> 6;
                const int d = nloc & 63;
                const float v0 = acc[mtl][nt][rh * 2 + 0] + bias[nloc];
                const float v1 = acc[mtl][nt][rh * 2 + 1] + bias[nloc + 1];
                const size_t idx = ((size_t)((bb * 16 + head) * 4096 + sq)) * 64 + d;
                *reinterpret_cast<float2*>(outm + idx) = make_float2(v0, v1);
            }
        }
    }
}

// ---------------- launch ----------------
extern "C" void kernel_launch(void* const* d_in, const int* in_sizes, int n_in,
                              void* d_out, int out_size) {
    const float* X  = (const float*)d_in[0];
    const float* Wq = (const float*)d_in[1];
    const float* bq = (const float*)d_in[2];
    const float* Wk = (const float*)d_in[3];
    const float* bk = (const float*)d_in[4];
    const float* Wv = (const float*)d_in[5];
    const float* bv = (const float*)d_in[6];
    float* out = (float*)d_out;

    prep_a<<<8192, 256>>>(X);
    prep_b<<<1536, 256>>>(Wq, Wk, Wv);

    cudaFuncSetAttribute(qkv_f16_mma,
                         cudaFuncAttributeMaxDynamicSharedMemorySize, SMEM_TOTAL);
    qkv_f16_mma<<<dim3(24, 128), 128, SMEM_TOTAL>>>(bq, bk, bv, out);
}